// round 9
// baseline (speedup 1.0000x reference)
#include <cuda_runtime.h>
#include <cstdint>

// CubePadding: x [B=4, 6, C=64, H=128, W=128] f32 -> out [B, 6, C, 132, 132] f32
// One block per 33-output-row chunk (4 chunks per face-channel, all uniform).
// Block assembles its 33x132 chunk (17424 B, contiguous & 16B-aligned in the
// output) in shared memory — interior rows via coalesced 512B row loads, halo
// rows / edge pads via scalar gathers — then emits it with a single
// cp.async.bulk shared->global (TMA) store: perfect write coalescing.

#define Pp 2
#define Bn 4
#define Cn 64
#define Hn 128
#define Wn 128
#define OH 132
#define OW 132
#define CHUNK_ROWS 33
#define CHUNK_FLOATS (CHUNK_ROWS * OW)        // 4356
#define CHUNK_BYTES (CHUNK_FLOATS * 4)        // 17424 (16B multiple)
#define NG (Bn * 6 * Cn)                      // 1536
#define TOTAL_BLOCKS (NG * 4)                 // 6144

// face ids: 0=back(fb) 1=down(fd) 2=front(ff) 3=left(fl) 4=right(fr) 5=top(ft)

__device__ __forceinline__ void top_map(int f, int i, int j, int& sf, int& sh, int& sw) {
    switch (f) {
        case 0: sf = 5; sh = Pp - 1 - i;  sw = j;           break;
        case 1: sf = 2; sh = Hn - Pp + i; sw = j;           break;
        case 2: sf = 5; sh = Hn - Pp + i; sw = j;           break;
        case 3: sf = 5; sh = j;           sw = i;           break;
        case 4: sf = 5; sh = j;           sw = Wn - 1 - i;  break;
        default: sf = 0; sh = Pp - 1 - i; sw = j;           break;
    }
}

__device__ __forceinline__ void bot_map(int f, int i, int j, int& sf, int& sh, int& sw) {
    switch (f) {
        case 0: sf = 1; sh = Hn - 1 - i;  sw = j;           break;
        case 1: sf = 0; sh = Hn - 1 - i;  sw = j;           break;
        case 2: sf = 1; sh = i;           sw = j;           break;
        case 3: sf = 1; sh = j;           sw = Pp - 1 - i;  break;
        case 4: sf = 1; sh = j;           sw = Wn - Pp + i; break;
        default: sf = 2; sh = i;          sw = j;           break;
    }
}

__device__ __forceinline__ void lft_map(int f, int r, int i, int& sf, int& sh, int& sw) {
    switch (f) {
        case 0: sf = 4; sh = r;           sw = Wn - Pp + i; break;
        case 1: sf = 3; sh = Hn - 1 - i;  sw = r;           break;
        case 2: sf = 3; sh = r;           sw = Wn - Pp + i; break;
        case 3: sf = 0; sh = r;           sw = Wn - Pp + i; break;
        case 4: sf = 2; sh = r;           sw = Wn - Pp + i; break;
        default: sf = 3; sh = i;          sw = r;           break;
    }
}

__device__ __forceinline__ void rgt_map(int f, int r, int i, int& sf, int& sh, int& sw) {
    switch (f) {
        case 0: sf = 3; sh = r;           sw = i;           break;
        case 1: sf = 4; sh = Hn - Pp + i; sw = r;           break;
        case 2: sf = 4; sh = r;           sw = i;           break;
        case 3: sf = 2; sh = r;           sw = i;           break;
        case 4: sf = 0; sh = r;           sw = i;           break;
        default: sf = 4; sh = Pp - 1 - i; sw = r;           break;
    }
}

__device__ __forceinline__ void src_map(int f, int ho, int wo, int& sf, int& sh, int& sw) {
    if (wo >= Pp && wo < Pp + Wn) {
        int j = wo - Pp;
        if (ho < Pp)                top_map(f, ho, j, sf, sh, sw);
        else if (ho >= Pp + Hn)     bot_map(f, ho - Pp - Hn, j, sf, sh, sw);
        else { sf = f; sh = ho - Pp; sw = j; }
    } else if (wo < Pp) {
        if (ho < Pp)                top_map(f, ho, 0, sf, sh, sw);
        else if (ho >= Pp + Hn)     bot_map(f, ho - Pp - Hn, 0, sf, sh, sw);
        else                        lft_map(f, ho - Pp, wo, sf, sh, sw);
    } else {
        if (ho < Pp)                top_map(f, ho, Wn - 1, sf, sh, sw);
        else if (ho >= Pp + Hn)     bot_map(f, ho - Pp - Hn, Wn - 1, sf, sh, sw);
        else                        rgt_map(f, ho - Pp, wo - Pp - Wn, sf, sh, sw);
    }
}

__device__ __forceinline__ float gather1(const float* __restrict__ x,
                                         int b, int f, int c, int ho, int wo) {
    int sf, sh, sw;
    src_map(f, ho, wo, sf, sh, sw);
    return __ldg(x + ((size_t)((b * 6 + sf) * Cn + c)) * (Hn * Wn) + sh * Wn + sw);
}

__global__ void __launch_bounds__(256)
cube_pad(const float* __restrict__ x, float* __restrict__ out) {
    __shared__ __align__(16) float sbuf[CHUNK_FLOATS];

    unsigned g  = blockIdx.x >> 2;            // face-channel
    int      q  = blockIdx.x & 3;             // quarter (33 output rows)
    int      ho0 = q * CHUNK_ROWS;

    int warp = threadIdx.x >> 5;
    int lane = threadIdx.x & 31;

    int b_ = g / (6 * Cn);
    int f  = (g / Cn) % 6;
    int c  = g % Cn;

    const float* xg = x + ((size_t)g << 14);  // this face-channel's input

    for (int rl = warp; rl < CHUNK_ROWS; rl += 8) {
        int ho = ho0 + rl;
        float* srow = sbuf + rl * OW;

        if (ho >= Pp && ho < Pp + Hn) {
            // interior row: coalesced 512B load, realigned into smem
            float4 a = __ldg((const float4*)(xg + (ho - Pp) * Wn) + lane);
            float2* d = (float2*)(srow + 2 + 4 * lane);   // 8B-aligned
            d[0] = make_float2(a.x, a.y);
            d[1] = make_float2(a.z, a.w);
            if (lane == 0) {
                srow[0] = gather1(x, b_, f, c, ho, 0);
                srow[1] = gather1(x, b_, f, c, ho, 1);
            } else if (lane == 31) {
                srow[130] = gather1(x, b_, f, c, ho, 130);
                srow[131] = gather1(x, b_, f, c, ho, 131);
            }
        } else {
            // halo row (ho in {0,1,130,131}): full gather
            int wo = 4 * lane;
            srow[wo + 0] = gather1(x, b_, f, c, ho, wo + 0);
            srow[wo + 1] = gather1(x, b_, f, c, ho, wo + 1);
            srow[wo + 2] = gather1(x, b_, f, c, ho, wo + 2);
            srow[wo + 3] = gather1(x, b_, f, c, ho, wo + 3);
            if (lane == 31) {
                srow[128] = gather1(x, b_, f, c, ho, 128);
                srow[129] = gather1(x, b_, f, c, ho, 129);
                srow[130] = gather1(x, b_, f, c, ho, 130);
                srow[131] = gather1(x, b_, f, c, ho, 131);
            }
        }
    }

    __syncthreads();

    if (threadIdx.x == 0) {
        // generic smem writes -> async proxy, then one contiguous TMA store
        asm volatile("fence.proxy.async.shared::cta;" ::: "memory");
        uint32_t saddr;
        asm("{ .reg .u64 t; cvta.to.shared.u64 t, %1; cvt.u32.u64 %0, t; }"
            : "=r"(saddr) : "l"(sbuf));
        const float* gdst = out + (size_t)blockIdx.x * CHUNK_FLOATS;
        asm volatile(
            "cp.async.bulk.global.shared::cta.bulk_group [%0], [%1], %2;"
            :: "l"(gdst), "r"(saddr), "r"((uint32_t)CHUNK_BYTES) : "memory");
        asm volatile("cp.async.bulk.commit_group;" ::: "memory");
        asm volatile("cp.async.bulk.wait_group 0;" ::: "memory");
    }
}

extern "C" void kernel_launch(void* const* d_in, const int* in_sizes, int n_in,
                              void* d_out, int out_size) {
    const float* x = (const float*)d_in[0];
    cube_pad<<<TOTAL_BLOCKS, 256>>>(x, (float*)d_out);
}

// round 10
// speedup vs baseline: 1.7210x; 1.7210x over previous
#include <cuda_runtime.h>

// CubePadding: x [B=4, 6, C=64, H=128, W=128] f32 -> out [B, 6, C, 132, 132] f32
// Final (measured-best, R7 config): single kernel, boundary (halo gather) and
// interior (streaming copy) blocks interleaved in groups of 353 (97 boundary +
// 256 interior, exact x24) so DRAM stays saturated throughout. Interior:
// warp-per-4-rows (MLP=4), shuffle-realigned, streaming float4 stores.
// 8 blocks/SM. ~208 MB compulsory traffic at ~6.8 TB/s effective (~85% spec).

#define Pp 2
#define Bn 4
#define Cn 64
#define Hn 128
#define Wn 128
#define OH 132
#define OW 132

#define NG        (Bn * 6 * Cn)               // 1536 face-channels
#define ROWS_PER_WARP 4
#define INT_WARPS (NG * Hn / ROWS_PER_WARP)   // 49152
#define INT_BLOCKS (INT_WARPS / 8)            // 6144
#define BND_PER_G (4 * 33 + Hn * 2)           // 388 boundary float4s per g
#define BND_TOTAL (NG * BND_PER_G)            // 595968 (= 2328 * 256 exactly)
#define BND_BLOCKS (BND_TOTAL / 256)          // 2328
#define GRP_BND   97
#define GRP_INT   256
#define GRP_SIZE  (GRP_BND + GRP_INT)         // 353
#define TOTAL_BLOCKS (INT_BLOCKS + BND_BLOCKS) // 8472 = 24 * 353

// face ids: 0=back(fb) 1=down(fd) 2=front(ff) 3=left(fl) 4=right(fr) 5=top(ft)

__device__ __forceinline__ void top_map(int f, int i, int j, int& sf, int& sh, int& sw) {
    switch (f) {
        case 0: sf = 5; sh = Pp - 1 - i;  sw = j;           break;
        case 1: sf = 2; sh = Hn - Pp + i; sw = j;           break;
        case 2: sf = 5; sh = Hn - Pp + i; sw = j;           break;
        case 3: sf = 5; sh = j;           sw = i;           break;
        case 4: sf = 5; sh = j;           sw = Wn - 1 - i;  break;
        default: sf = 0; sh = Pp - 1 - i; sw = j;           break;
    }
}

__device__ __forceinline__ void bot_map(int f, int i, int j, int& sf, int& sh, int& sw) {
    switch (f) {
        case 0: sf = 1; sh = Hn - 1 - i;  sw = j;           break;
        case 1: sf = 0; sh = Hn - 1 - i;  sw = j;           break;
        case 2: sf = 1; sh = i;           sw = j;           break;
        case 3: sf = 1; sh = j;           sw = Pp - 1 - i;  break;
        case 4: sf = 1; sh = j;           sw = Wn - Pp + i; break;
        default: sf = 2; sh = i;          sw = j;           break;
    }
}

__device__ __forceinline__ void lft_map(int f, int r, int i, int& sf, int& sh, int& sw) {
    switch (f) {
        case 0: sf = 4; sh = r;           sw = Wn - Pp + i; break;
        case 1: sf = 3; sh = Hn - 1 - i;  sw = r;           break;
        case 2: sf = 3; sh = r;           sw = Wn - Pp + i; break;
        case 3: sf = 0; sh = r;           sw = Wn - Pp + i; break;
        case 4: sf = 2; sh = r;           sw = Wn - Pp + i; break;
        default: sf = 3; sh = i;          sw = r;           break;
    }
}

__device__ __forceinline__ void rgt_map(int f, int r, int i, int& sf, int& sh, int& sw) {
    switch (f) {
        case 0: sf = 3; sh = r;           sw = i;           break;
        case 1: sf = 4; sh = Hn - Pp + i; sw = r;           break;
        case 2: sf = 4; sh = r;           sw = i;           break;
        case 3: sf = 2; sh = r;           sw = i;           break;
        case 4: sf = 0; sh = r;           sw = i;           break;
        default: sf = 4; sh = Pp - 1 - i; sw = r;           break;
    }
}

__device__ __forceinline__ void src_map(int f, int ho, int wo, int& sf, int& sh, int& sw) {
    if (wo >= Pp && wo < Pp + Wn) {
        int j = wo - Pp;
        if (ho < Pp)                top_map(f, ho, j, sf, sh, sw);
        else if (ho >= Pp + Hn)     bot_map(f, ho - Pp - Hn, j, sf, sh, sw);
        else { sf = f; sh = ho - Pp; sw = j; }
    } else if (wo < Pp) {
        if (ho < Pp)                top_map(f, ho, 0, sf, sh, sw);
        else if (ho >= Pp + Hn)     bot_map(f, ho - Pp - Hn, 0, sf, sh, sw);
        else                        lft_map(f, ho - Pp, wo, sf, sh, sw);
    } else {
        if (ho < Pp)                top_map(f, ho, Wn - 1, sf, sh, sw);
        else if (ho >= Pp + Hn)     bot_map(f, ho - Pp - Hn, Wn - 1, sf, sh, sw);
        else                        rgt_map(f, ho - Pp, wo - Pp - Wn, sf, sh, sw);
    }
}

__device__ __forceinline__ float gather1(const float* __restrict__ x,
                                         int b, int f, int c, int ho, int wo) {
    int sf, sh, sw;
    src_map(f, ho, wo, sf, sh, sw);
    return __ldg(x + ((size_t)((b * 6 + sf) * Cn + c)) * (Hn * Wn) + sh * Wn + sw);
}

__global__ void __launch_bounds__(256, 8)
cube_pad(const float* __restrict__ x, float4* __restrict__ out4) {
    unsigned grp = blockIdx.x / GRP_SIZE;
    unsigned r   = blockIdx.x - grp * GRP_SIZE;

    if (r >= GRP_BND) {
        // ---------------- interior: warp-per-4-rows ----------------
        unsigned iblk = grp * GRP_INT + (r - GRP_BND);           // < INT_BLOCKS
        unsigned warp = threadIdx.x >> 5;
        unsigned lane = threadIdx.x & 31;
        unsigned idx  = iblk * 8u + warp;                        // < INT_WARPS
        unsigned g    = idx >> 5;                                // 32 row-quads per g
        unsigned h0   = (idx & 31u) * ROWS_PER_WARP;

        const float4* src4 = (const float4*)(x + ((size_t)g << 14)) + h0 * (Wn / 4) + lane;
        float4 a0 = __ldg(src4);
        float4 a1 = __ldg(src4 + 32);
        float4 a2 = __ldg(src4 + 64);
        float4 a3 = __ldg(src4 + 96);

        float4* dst = out4 + (size_t)g * (OH * 33) + (h0 + Pp) * 33 + (lane + 1);

        float nx, ny;
        nx = __shfl_down_sync(0xffffffffu, a0.x, 1);
        ny = __shfl_down_sync(0xffffffffu, a0.y, 1);
        if (lane < 31) __stcs(dst,      make_float4(a0.z, a0.w, nx, ny));
        nx = __shfl_down_sync(0xffffffffu, a1.x, 1);
        ny = __shfl_down_sync(0xffffffffu, a1.y, 1);
        if (lane < 31) __stcs(dst + 33, make_float4(a1.z, a1.w, nx, ny));
        nx = __shfl_down_sync(0xffffffffu, a2.x, 1);
        ny = __shfl_down_sync(0xffffffffu, a2.y, 1);
        if (lane < 31) __stcs(dst + 66, make_float4(a2.z, a2.w, nx, ny));
        nx = __shfl_down_sync(0xffffffffu, a3.x, 1);
        ny = __shfl_down_sync(0xffffffffu, a3.y, 1);
        if (lane < 31) __stcs(dst + 99, make_float4(a3.z, a3.w, nx, ny));
        return;
    }

    // ---------------- boundary: per-float4 gather ----------------
    unsigned bblk = grp * GRP_BND + r;                           // < BND_BLOCKS
    unsigned bt = bblk * 256u + threadIdx.x;
    if (bt >= BND_TOTAL) return;

    unsigned g = bt / BND_PER_G;
    unsigned k = bt - g * BND_PER_G;

    int ho, w4;
    if (k < 132) {                      // full rows ho in {0,1,130,131}
        unsigned rr = k / 33u;
        w4 = k - rr * 33u;
        ho = (rr < 2) ? (int)rr : (int)(rr + 128);
    } else {                            // interior rows, edge float4s (w4 0 / 32)
        unsigned k2 = k - 132;
        ho = (int)(k2 >> 1) + Pp;
        w4 = (k2 & 1) ? 32 : 0;
    }

    int b_ = g / (6 * Cn);
    int f  = (g / Cn) % 6;
    int c  = g % Cn;
    int wo = w4 * 4;

    float4 v;
    v.x = gather1(x, b_, f, c, ho, wo + 0);
    v.y = gather1(x, b_, f, c, ho, wo + 1);
    v.z = gather1(x, b_, f, c, ho, wo + 2);
    v.w = gather1(x, b_, f, c, ho, wo + 3);

    out4[(size_t)g * (OH * 33) + ho * 33 + w4] = v;
}

extern "C" void kernel_launch(void* const* d_in, const int* in_sizes, int n_in,
                              void* d_out, int out_size) {
    const float* x = (const float*)d_in[0];
    cube_pad<<<TOTAL_BLOCKS, 256>>>(x, (float4*)d_out);
}